// round 1
// baseline (speedup 1.0000x reference)
#include <cuda_runtime.h>

#define SS 192
#define SPAD 193            // padded row stride: 193 % 32 == 1 -> conflict-free column access
#define NEGINF (-1e30f)

__device__ __forceinline__ float softplusf(float x) {
    // stable: max(x,0) + log1p(exp(-|x|))
    return fmaxf(x, 0.f) + log1pf(__expf(-fabsf(x)));
}

__global__ __launch_bounds__(1024, 1)
void cky_fwd_bwd_kernel(const float* __restrict__ rules,
                        const int*   __restrict__ lens,
                        float* __restrict__ Zout,
                        float* __restrict__ marg)
{
    extern __shared__ float C[];   // [SS][SPAD]: upper triangle + diag = inside scores a[i,j];
                                   // strict lower triangle (after bwd pass) = q[i,j] stored at [j][i]
    const int b = blockIdx.x;
    const float* __restrict__ R = rules + (size_t)b * SS * SS;
    float* __restrict__ M = marg + (size_t)b * SS * SS;
    const int tid  = threadIdx.x;
    const int lane = tid & 31;
    const int wid  = tid >> 5;
    const int L = lens[b];

    // zero the marginal slab (d_out is poisoned; lower triangle must be 0)
    for (int t = tid; t < SS * SS; t += 1024) M[t] = 0.f;

    // diagonal init: a[i,i] = softplus(r[i,i])
    for (int i = tid; i < SS; i += 1024) C[i * SPAD + i] = softplusf(R[i * SS + i]);
    __syncthreads();

    // ---------------- forward (inside), increasing width ----------------
    for (int w = 1; w < SS; ++w) {
        const int n = SS - w;                 // spans of this width
        const int nu = (w + 31) >> 5;         // register-chunks per span (<= 6)
        for (int i = wid; i < n; i += 32) {   // warp per span
            const int j = i + w;
            float v[6];
            float m = NEGINF;
            #pragma unroll
            for (int u = 0; u < 6; ++u) {
                if (u < nu) {
                    int k = i + lane + (u << 5);
                    float x = (k < j) ? (C[i * SPAD + k] + C[(k + 1) * SPAD + j]) : NEGINF;
                    v[u] = x;
                    m = fmaxf(m, x);
                }
            }
            #pragma unroll
            for (int o = 16; o; o >>= 1)
                m = fmaxf(m, __shfl_xor_sync(0xffffffffu, m, o));
            float s = 0.f;
            #pragma unroll
            for (int u = 0; u < 6; ++u) {
                if (u < nu) s += __expf(v[u] - m);
            }
            #pragma unroll
            for (int o = 16; o; o >>= 1)
                s += __shfl_xor_sync(0xffffffffu, s, o);
            if (lane == 0)
                C[i * SPAD + j] = softplusf(R[i * SS + j]) + m + __logf(s);
        }
        __syncthreads();
    }

    if (tid == 0) Zout[b] = C[0 * SPAD + (L - 1)];
    __syncthreads();

    // ---------------- backward (outside / marginals), decreasing width ----------------
    // g[i,j] = sum over parents; q[i,j] = log(g) - lse[i,j], lse = a - softplus(r)
    // Parents of (i,j):
    //   as LEFT child of (i, j'), j' > j :  exp(a[i,j] + a[j+1,j'] + q[i,j'])
    //   as RIGHT child of (i', j), i' < i:  exp(a[i,j] + a[i',i-1] + q[i',j])
    // q of width > w read from C's lower triangle (written in earlier iterations);
    // a of width < w read from C's intact upper triangle. No hazards within a width.
    for (int w = SS - 1; w >= 0; --w) {
        const int n = SS - w;
        for (int i = wid; i < n; i += 32) {   // warp per cell
            const int j = i + w;
            const float aij = C[i * SPAD + j];
            const int nR = SS - 1 - j;        // # right-extension parents
            const int T = nR + i;             // total parent terms
            float s = 0.f;
            for (int t = lane; t < T; t += 32) {
                float val;
                if (t < nR) {
                    int j2 = j + 1 + t;
                    val = C[(j + 1) * SPAD + j2] + C[j2 * SPAD + i];   // a[j+1,j'] + q[i,j']
                } else {
                    int i2 = t - nR;
                    val = C[i2 * SPAD + (i - 1)] + C[j * SPAD + i2];   // a[i',i-1] + q[i',j]
                }
                s += __expf(aij + val);
            }
            #pragma unroll
            for (int o = 16; o; o >>= 1)
                s += __shfl_xor_sync(0xffffffffu, s, o);
            if (lane == 0) {
                float g = s + ((i == 0 && j == L - 1) ? 1.f : 0.f);
                float r = R[i * SS + j];
                float sig = 1.f / (1.f + __expf(-r));
                M[i * SS + j] = g * sig;      // d Z / d r[i,j] = g * sigmoid(r)
                if (i < j) {                  // diagonal cells are never parents -> keep a[i,i]
                    float q = (g > 0.f) ? (__logf(g) - (aij - softplusf(r))) : NEGINF;
                    C[j * SPAD + i] = fmaxf(q, NEGINF);
                }
            }
        }
        __syncthreads();
    }
}

extern "C" void kernel_launch(void* const* d_in, const int* in_sizes, int n_in,
                              void* d_out, int out_size) {
    const float* rules = (const float*)d_in[0];   // (16,192,192,1) fp32
    const int*   lens  = (const int*)d_in[1];     // (16,) int32
    float* Z = (float*)d_out;                     // first 16 floats
    float* M = (float*)d_out + 16;                // then (16,192,192) marginal

    const int smem = SS * SPAD * (int)sizeof(float);   // 148224 B
    static bool attr_set = false;
    // setting an attribute is idempotent and not a stream operation; do it every call
    cudaFuncSetAttribute(cky_fwd_bwd_kernel,
                         cudaFuncAttributeMaxDynamicSharedMemorySize, smem);
    (void)attr_set; (void)in_sizes; (void)n_in; (void)out_size;

    cky_fwd_bwd_kernel<<<16, 1024, smem>>>(rules, lens, Z, M);
}